// round 5
// baseline (speedup 1.0000x reference)
#include <cuda_runtime.h>

// ---------------- problem constants ----------------
#define NBATCH 512
#define HID    512
#define GATES  2048           // 4*HID
#define DDIM   9
#define TENC   257            // encode steps (T+1)
#define TDEC   256            // decode steps
#define NSTEPS 513            // TENC + TDEC

// ---------------- tiling ----------------
#define MB 4                  // batch blocks
#define JB 32                 // hidden-unit blocks
#define NCTA (MB*JB)          // 128 CTAs, 1 per SM, all resident
#define NCTA_GRP JB           // CTAs per barrier group (share one batch block)
#define MT 128                // batch rows per CTA
#define JT 16                 // hidden units per CTA
#define CT 64                 // gate columns per CTA = 4*JT
#define KC 16                 // k-chunk
#define NCHUNK (HID/KC)       // 32
#define NTHREADS 512

#define HS_STRIDE 132         // padded row stride (16B-aligned rows, conflict-free)
#define HS_BUF (KC*HS_STRIDE) // 2112
#define XS_STRIDE 12

// smem layout in floats
#define WS_OFF   0
#define HS_OFF   (WS_OFF + HID*CT)            // 32768
#define XS_OFF   (HS_OFF + 2*HS_BUF)          // +4224
#define WIH_OFF  (XS_OFF + MT*XS_STRIDE)      // +1536
#define BIAS_OFF (WIH_OFF + CT*XS_STRIDE)     // +768
#define SMEM_FLOATS (BIAS_OFF + CT)
#define SMEM_BYTES  (SMEM_FLOATS*4)           // ~157.4 KB

typedef unsigned long long ull;

// ---------------- device globals ----------------
__device__ __align__(16) float g_h[2][NBATCH*HID];   // double-buffered hidden state
__device__ unsigned g_cnt[4*32];   // one counter per mi-group, padded 128B apart
__device__ unsigned g_gen[4*32];

// ---------------- helpers ----------------
__device__ __forceinline__ float sigf(float x) { return 1.0f / (1.0f + __expf(-x)); }

__device__ __forceinline__ ull pack2(float lo, float hi) {
    ull r; asm("mov.b64 %0, {%1,%2};" : "=l"(r) : "f"(lo), "f"(hi)); return r;
}
__device__ __forceinline__ void unpack2(ull v, float& lo, float& hi) {
    asm("mov.b64 {%0,%1}, %2;" : "=f"(lo), "=f"(hi) : "l"(v));
}
__device__ __forceinline__ ull dup2(float x) {
    ull r; asm("mov.b64 %0, {%1,%1};" : "=l"(r) : "f"(x)); return r;
}
__device__ __forceinline__ void ffma2(ull& acc, ull a, ull b) {
    asm("fma.rn.f32x2 %0, %1, %2, %0;" : "+l"(acc) : "l"(a), "l"(b));
}

// barrier over the 32 CTAs of one mi-group
__device__ __forceinline__ void group_sync(int mi) {
    __syncthreads();
    if (threadIdx.x == 0) {
        __threadfence();
        volatile unsigned* genp = &g_gen[mi * 32];
        unsigned target = *genp + 1u;
        if (atomicAdd(&g_cnt[mi * 32], 1u) == NCTA_GRP - 1u) {
            atomicExch(&g_cnt[mi * 32], 0u);
            __threadfence();
            atomicExch((unsigned*)&g_gen[mi * 32], target);
        } else {
            while ((int)(*genp - target) < 0) { }
        }
        __threadfence();
    }
    __syncthreads();
}

// FC head: 4 rows x 9 outputs per CTA, one output per warp-slot, lane-parallel over k
__device__ __forceinline__ void fc_out(const float* __restrict__ h,
                                       const float* __restrict__ fcW,
                                       const float* __restrict__ fcb,
                                       float* __restrict__ out,
                                       int n0, int td, int wid, int lane) {
    for (int o = wid; o < 4 * DDIM; o += 16) {
        int rr = o / DDIM, d = o - rr * DDIM;
        int n = n0 + rr;
        const float* hr = h + (size_t)n * HID;
        const float* wr = fcW + d * HID;
        float s = 0.0f;
#pragma unroll
        for (int j = 0; j < 16; ++j)
            s += __ldcg(hr + j * 32 + lane) * wr[j * 32 + lane];
#pragma unroll
        for (int off = 16; off; off >>= 1)
            s += __shfl_xor_sync(0xffffffffu, s, off);
        if (lane == 0)
            out[((size_t)n * TDEC + td) * DDIM + d] = sigf(s + fcb[d]);
    }
}

// ---------------- persistent kernel ----------------
__global__ void __launch_bounds__(NTHREADS, 1)
lstm_kernel(const float* __restrict__ x, const float* __restrict__ W_ih,
            const float* __restrict__ W_hh, const float* __restrict__ b_ih,
            const float* __restrict__ b_hh, const float* __restrict__ fcW,
            const float* __restrict__ fcb, const float* __restrict__ h0,
            const float* __restrict__ c0, float* __restrict__ out) {
    extern __shared__ float sm[];
    float* ws   = sm + WS_OFF;    // [512][64] gate weights, col c = u*4+q
    float* hs   = sm + HS_OFF;    // double-buffered h tile [2][16][132]
    float* xs   = sm + XS_OFF;    // [128][12] x tile
    float* wih  = sm + WIH_OFF;   // [64][12]
    float* bias = sm + BIAS_OFF;  // [64] = b_ih + b_hh

    const int tid = threadIdx.x;
    const int bx  = blockIdx.x;
    const int mi = bx >> 5, ji = bx & 31;
    const int m0 = mi * MT;
    const int j0 = ji * JT;
    const int tx = tid & 15;      // hidden unit within block
    const int ty = tid >> 4;      // row group (0..31)
    const int r0 = ty * 4;        // 4 rows per thread
    const int lane = tid & 31;
    const int wid  = tid >> 5;

    // staging indices: one float4 per thread per chunk
    const int srow = tid >> 2;          // 0..127
    const int sk4  = (tid & 3) << 2;    // 0,4,8,12

    // ---- one-time loads (weights resident in smem for the whole run) ----
    for (int idx = tid; idx < CT * HID; idx += NTHREADS) {
        int c = idx >> 9;
        int k = idx & 511;
        int g = (c & 3) * HID + j0 + (c >> 2);
        ws[k * CT + c] = W_hh[(size_t)g * HID + k];
    }
    for (int idx = tid; idx < CT * DDIM; idx += NTHREADS) {
        int c = idx / DDIM, d = idx - c * DDIM;
        int g = (c & 3) * HID + j0 + (c >> 2);
        wih[c * XS_STRIDE + d] = W_ih[g * DDIM + d];
    }
    for (int c = tid; c < CT; c += NTHREADS) {
        int g = (c & 3) * HID + j0 + (c >> 2);
        bias[c] = b_ih[g] + b_hh[g];
    }
    // init h buffer 0 with broadcast h0 (this CTA's owned region)
    for (int idx = tid; idx < MT * JT; idx += NTHREADS) {
        int r = idx >> 4;
        int j = idx & 15;
        g_h[0][(size_t)(m0 + r) * HID + j0 + j] = h0[j0 + j];
    }
    float c_reg[4];
    {
        float ci = c0[j0 + tx];
#pragma unroll
        for (int r = 0; r < 4; ++r) c_reg[r] = ci;
    }
    __syncthreads();
    group_sync(mi);

    // ---- time loop: 257 encode + 256 decode ----
    for (int s = 0; s < NSTEPS; ++s) {
        const int rb = s & 1;
        const float* __restrict__ hin  = g_h[rb];
        float* __restrict__       hout = g_h[rb ^ 1];

        // prefetch chunk 0 early
        float4 pf = __ldcg((const float4*)(hin + (size_t)(m0 + srow) * HID + sk4));

        if (s >= TENC + 1)                        // emit previous decode step's output
            fc_out(hin, fcW, fcb, out, m0 + (ji << 2), s - (TENC + 1), wid, lane);

        const bool enc = (s < TENC);
        if (enc) {
            for (int idx = tid; idx < MT * DDIM; idx += NTHREADS) {
                int r = idx / DDIM, d = idx - r * DDIM;
                xs[r * XS_STRIDE + d] =
                    x[(size_t)(m0 + r) * (TENC * DDIM) + s * DDIM + d];
            }
        }
        // stage chunk 0 -> buf 0 (transposed: hs[k][row])
        {
            float* hb = hs;
            hb[(sk4 + 0) * HS_STRIDE + srow] = pf.x;
            hb[(sk4 + 1) * HS_STRIDE + srow] = pf.y;
            hb[(sk4 + 2) * HS_STRIDE + srow] = pf.z;
            hb[(sk4 + 3) * HS_STRIDE + srow] = pf.w;
        }
        __syncthreads();

        // gate accumulators: 2 row-pairs x 4 gates, packed f32x2 over (even,odd) rows
        ull acc[2][4];
#pragma unroll
        for (int rp = 0; rp < 2; ++rp) {
#pragma unroll
            for (int q = 0; q < 4; ++q) {
                float b = bias[tx * 4 + q];
                float lo = b, hi = b;
                if (enc) {
#pragma unroll
                    for (int d = 0; d < DDIM; ++d) {
                        float w = wih[(tx * 4 + q) * XS_STRIDE + d];
                        lo += xs[(r0 + 2 * rp) * XS_STRIDE + d] * w;
                        hi += xs[(r0 + 2 * rp + 1) * XS_STRIDE + d] * w;
                    }
                }
                acc[rp][q] = pack2(lo, hi);
            }
        }

        // main GEMM: gates[128x64] += h[128x512] * Whh_block[64x512]^T
        for (int ch = 0; ch < NCHUNK; ++ch) {
            if (ch + 1 < NCHUNK)
                pf = __ldcg((const float4*)(hin + (size_t)(m0 + srow) * HID
                                            + (ch + 1) * KC + sk4));
            const float* wsb = ws + (ch * KC) * CT + (tx << 2);
            const float* hsb = hs + (ch & 1) * HS_BUF + r0;
#pragma unroll
            for (int kk = 0; kk < KC; ++kk) {
                float4 b4 = *(const float4*)(wsb + kk * CT);     // LDS.128: i,f,g,o of unit tx
                ulonglong2 a2 = *(const ulonglong2*)(hsb + kk * HS_STRIDE); // LDS.128: 4 rows
                ull b0 = dup2(b4.x), b1 = dup2(b4.y), b2 = dup2(b4.z), b3 = dup2(b4.w);
                ffma2(acc[0][0], a2.x, b0);
                ffma2(acc[0][1], a2.x, b1);
                ffma2(acc[0][2], a2.x, b2);
                ffma2(acc[0][3], a2.x, b3);
                ffma2(acc[1][0], a2.y, b0);
                ffma2(acc[1][1], a2.y, b1);
                ffma2(acc[1][2], a2.y, b2);
                ffma2(acc[1][3], a2.y, b3);
            }
            if (ch + 1 < NCHUNK) {
                float* hb = hs + ((ch + 1) & 1) * HS_BUF;
                hb[(sk4 + 0) * HS_STRIDE + srow] = pf.x;
                hb[(sk4 + 1) * HS_STRIDE + srow] = pf.y;
                hb[(sk4 + 2) * HS_STRIDE + srow] = pf.z;
                hb[(sk4 + 3) * HS_STRIDE + srow] = pf.w;
            }
            __syncthreads();
        }

        // pointwise LSTM cell update (CTA-local: this CTA owns (rows, units) block)
#pragma unroll
        for (int rp = 0; rp < 2; ++rp) {
            float ie, io, fe, fo, ge, go, oe, oo;
            unpack2(acc[rp][0], ie, io);
            unpack2(acc[rp][1], fe, fo);
            unpack2(acc[rp][2], ge, go);
            unpack2(acc[rp][3], oe, oo);
            float ce = sigf(fe) * c_reg[2 * rp]     + sigf(ie) * tanhf(ge);
            float co = sigf(fo) * c_reg[2 * rp + 1] + sigf(io) * tanhf(go);
            c_reg[2 * rp]     = ce;
            c_reg[2 * rp + 1] = co;
            float he = sigf(oe) * tanhf(ce);
            float ho = sigf(oo) * tanhf(co);
            hout[(size_t)(m0 + r0 + 2 * rp)     * HID + j0 + tx] = he;
            hout[(size_t)(m0 + r0 + 2 * rp + 1) * HID + j0 + tx] = ho;
        }
        group_sync(mi);
    }

    // final decode step's output
    fc_out(g_h[NSTEPS & 1], fcW, fcb, out, m0 + (ji << 2), TDEC - 1, wid, lane);
}

// ---------------- launch ----------------
extern "C" void kernel_launch(void* const* d_in, const int* in_sizes, int n_in,
                              void* d_out, int out_size) {
    (void)in_sizes; (void)n_in; (void)out_size;
    cudaFuncSetAttribute(lstm_kernel, cudaFuncAttributeMaxDynamicSharedMemorySize,
                         SMEM_BYTES);
    lstm_kernel<<<NCTA, NTHREADS, SMEM_BYTES>>>(
        (const float*)d_in[0],   // x
        (const float*)d_in[1],   // W_ih
        (const float*)d_in[2],   // W_hh
        (const float*)d_in[3],   // b_ih
        (const float*)d_in[4],   // b_hh
        (const float*)d_in[5],   // fc_W
        (const float*)d_in[6],   // fc_b
        (const float*)d_in[7],   // h0
        (const float*)d_in[8],   // c0
        (float*)d_out);
}